// round 6
// baseline (speedup 1.0000x reference)
#include <cuda_runtime.h>
#include <math.h>

// ---------------------------------------------------------------------------
// TextureBaker — setup (per-triangle precompute + 8x8 coarse SAT mask) + bake
// (per 16x16-pixel tile: bbox&mask filter -> one stable compaction writing
// 48B records into smem -> per-pixel first-hit scan -> attr interpolation).
// Bake is launched with PDL so its prologue overlaps setup.
// Scan / interpolation FP expressions identical to prior passing kernels.
// ---------------------------------------------------------------------------

#define MAX_F  8192
#define TS     16

__device__ float4              g_rec [MAX_F * 3];  // [ax ay v0x v0y][v1x v1y d00 d01][d11 inv tid pad]
__device__ int4                g_ids [MAX_F];
__device__ float4              g_bbox[MAX_F];      // (minx, maxx, miny, maxy)
__device__ unsigned long long  g_mask[MAX_F];      // 8x8 coarse-tile SAT mask

// ----------------------------- SAT helper ---------------------------------
__device__ __forceinline__ bool rect_outside_edge(
    float px, float py, float qx, float qy, float rx, float ry,
    float x0, float y0, float x1, float y1)
{
    float ex = qx - px, ey = qy - py;
    float sr  = ex * (ry - py) - ey * (rx - px);
    float s00 = ex * (y0 - py) - ey * (x0 - px);
    float s01 = ex * (y1 - py) - ey * (x0 - px);
    float s10 = ex * (y0 - py) - ey * (x1 - px);
    float s11 = ex * (y1 - py) - ey * (x1 - px);
    float mx = fmaxf(fmaxf(s00, s01), fmaxf(s10, s11));
    float mn = fminf(fminf(s00, s01), fminf(s10, s11));
    if (sr > 0.0f) return mx < 0.0f;   // rect strictly on far side of edge
    if (sr < 0.0f) return mn > 0.0f;
    return false;                      // degenerate edge: keep (conservative)
}

// ------------------------------- setup ------------------------------------
__global__ void tb_setup_kernel(const float* __restrict__ uv,
                                const int*   __restrict__ fidx,
                                int nf)
{
    int t = blockIdx.x * blockDim.x + threadIdx.x;
    if (t >= nf) return;

    int i0 = fidx[3 * t + 0];
    int i1 = fidx[3 * t + 1];
    int i2 = fidx[3 * t + 2];

    float ax = uv[2 * i0], ay = uv[2 * i0 + 1];
    float bx = uv[2 * i1], by = uv[2 * i1 + 1];
    float cx = uv[2 * i2], cy = uv[2 * i2 + 1];

    float v0x = bx - ax, v0y = by - ay;
    float v1x = cx - ax, v1y = cy - ay;

    float d00 = v0x * v0x + v0y * v0y;
    float d01 = v0x * v1x + v0y * v1y;
    float d11 = v1x * v1x + v1y * v1y;
    float denom = d00 * d11 - d01 * d01;

    // Degenerate triangle -> NaN inv -> inside test always false (matches ref).
    float inv = (fabsf(denom) < 1e-12f) ? __int_as_float(0x7fc00000)
                                        : (1.0f / denom);

    g_rec[3 * t + 0] = make_float4(ax, ay, v0x, v0y);
    g_rec[3 * t + 1] = make_float4(v1x, v1y, d00, d01);
    g_rec[3 * t + 2] = make_float4(d11, inv, __int_as_float(t), 0.0f);
    g_ids[t] = make_int4(i0, i1, i2, 0);

    float4 bb;
    bb.x = fminf(ax, fminf(bx, cx));
    bb.y = fmaxf(ax, fmaxf(bx, cx));
    bb.z = fminf(ay, fminf(by, cy));
    bb.w = fmaxf(ay, fmaxf(by, cy));
    g_bbox[t] = bb;

    // 8x8 coarse-tile conservative SAT mask over UV [0,1]^2
    const float eps = 1e-5f;
    int cx0 = max(0, (int)floorf((bb.x - eps) * 8.0f));
    int cx1 = min(7, (int)floorf((bb.y + eps) * 8.0f));
    int cy0 = max(0, (int)floorf((bb.z - eps) * 8.0f));
    int cy1 = min(7, (int)floorf((bb.w + eps) * 8.0f));

    unsigned long long m = 0ull;
    for (int gy = cy0; gy <= cy1; gy++) {
        float ry0 = (float)gy * 0.125f - eps;
        float ry1 = (float)(gy + 1) * 0.125f + eps;
        for (int gx = cx0; gx <= cx1; gx++) {
            float rx0 = (float)gx * 0.125f - eps;
            float rx1 = (float)(gx + 1) * 0.125f + eps;
            bool sep =
                rect_outside_edge(ax, ay, bx, by, cx, cy, rx0, ry0, rx1, ry1) ||
                rect_outside_edge(bx, by, cx, cy, ax, ay, rx0, ry0, rx1, ry1) ||
                rect_outside_edge(cx, cy, ax, ay, bx, by, rx0, ry0, rx1, ry1);
            if (!sep) m |= 1ull << (gy * 8 + gx);
        }
    }
    g_mask[t] = m;
}

// -------------------------------- bake ------------------------------------
__global__ void __launch_bounds__(256)
tb_bake_kernel(const float* __restrict__ attr,
               int nf, int res, int ntx,
               float* __restrict__ out)
{
    __shared__ float4 s_rec[512 * 3];   // 24 KB: up to 512 48B records
    __shared__ int    s_tot[16];

    int tile = blockIdx.x;
    int tx = tile % ntx;
    int ty = tile / ntx;
    int tid  = threadIdx.x;
    int lane = tid & 31;
    int wid  = tid >> 5;
    unsigned lmask = (1u << lane) - 1u;

    const float eps = 1e-5f;
    float rinv = 1.0f / (float)res;
    float x0 = (float)(tx * TS)      * rinv - eps;
    float x1 = (float)(tx * TS + TS) * rinv + eps;
    float y0 = (float)(ty * TS)      * rinv - eps;
    float y1 = (float)(ty * TS + TS) * rinv + eps;

    // coarse-tile query mask for this tile
    int qx0 = max(0, (int)floorf(x0 * 8.0f));
    int qx1 = min(7, (int)floorf(x1 * 8.0f));
    int qy0 = max(0, (int)floorf(y0 * 8.0f));
    int qy1 = min(7, (int)floorf(y1 * 8.0f));
    unsigned long long qmask = 0ull;
    for (int gy = qy0; gy <= qy1; gy++)
        for (int gx = qx0; gx <= qx1; gx++)
            qmask |= 1ull << (gy * 8 + gx);

    int col = tx * TS + (tid & (TS - 1));
    int row = ty * TS + (tid >> 4);
    bool valid = (col < res) && (row < res);
    float pxx = ((float)col + 0.5f) * rinv;
    float pxy = ((float)row + 0.5f) * rinv;

    int   hitT = 0;
    float u = 0.0f, v = 0.0f, w = 0.0f;
    bool  found = false;

    // PDL: wait for setup kernel's outputs before touching g_* arrays.
    cudaGridDependencySynchronize();

    for (int chunk = 0; chunk < nf; chunk += 512) {
        __syncthreads();   // protect s_rec reuse across chunks

        int t0 = chunk + tid;
        int t1 = t0 + 256;
        bool k0 = false, k1 = false;
        if (t0 < nf) {
            float4 bb = g_bbox[t0];
            k0 = !(bb.x > x1 || bb.y < x0 || bb.z > y1 || bb.w < y0)
                 && (g_mask[t0] & qmask) != 0ull;
        }
        if (t1 < nf) {
            float4 bb = g_bbox[t1];
            k1 = !(bb.x > x1 || bb.y < x0 || bb.z > y1 || bb.w < y0)
                 && (g_mask[t1] & qmask) != 0ull;
        }

        unsigned b0 = __ballot_sync(0xffffffffu, k0);
        unsigned b1 = __ballot_sync(0xffffffffu, k1);
        if (lane == 0) { s_tot[wid] = __popc(b0); s_tot[8 + wid] = __popc(b1); }
        __syncthreads();

        int pre0 = 0, tot0 = 0, pre1 = 0, tot1 = 0;
        #pragma unroll
        for (int k = 0; k < 8; k++) {
            int a = s_tot[k], b = s_tot[8 + k];
            tot0 += a; tot1 += b;
            pre0 += (k < wid) ? a : 0;
            pre1 += (k < wid) ? b : 0;
        }

        if (k0) {
            int p = pre0 + __popc(b0 & lmask);
            s_rec[3 * p + 0] = g_rec[3 * t0 + 0];
            s_rec[3 * p + 1] = g_rec[3 * t0 + 1];
            s_rec[3 * p + 2] = g_rec[3 * t0 + 2];
        }
        if (k1) {
            int p = tot0 + pre1 + __popc(b1 & lmask);
            s_rec[3 * p + 0] = g_rec[3 * t1 + 0];
            s_rec[3 * p + 1] = g_rec[3 * t1 + 1];
            s_rec[3 * p + 2] = g_rec[3 * t1 + 2];
        }
        __syncthreads();
        int bn = tot0 + tot1;

        // ---- first-hit scan (early exit); order is original index order ----
        if (!found && valid) {
            for (int j = 0; j < bn; j++) {
                float4 q0 = s_rec[3 * j + 0];   // ax ay v0x v0y
                float4 q1 = s_rec[3 * j + 1];   // v1x v1y d00 d01
                float4 q2 = s_rec[3 * j + 2];   // d11 inv tid pad

                float v2x = pxx - q0.x;
                float v2y = pxy - q0.y;
                float d20 = v2x * q0.z + v2y * q0.w;
                float d21 = v2x * q1.x + v2y * q1.y;
                float vv  = (q2.x * d20 - q1.w * d21) * q2.y;
                float ww  = (q1.z * d21 - q1.w * d20) * q2.y;
                float uu  = 1.0f - vv - ww;
                if (uu >= 0.0f && vv >= 0.0f && ww >= 0.0f) {
                    found = true;
                    u = uu; v = vv; w = ww;
                    hitT = __float_as_int(q2.z);
                    break;
                }
            }
        }

        if (__syncthreads_and(found || !valid)) break;
    }

    if (!valid) return;

    float o0 = 0.0f, o1 = 0.0f, o2 = 0.0f;
    if (found) {
        int4 ids = g_ids[hitT];
        const float* a0 = attr + 3 * ids.x;
        const float* a1 = attr + 3 * ids.y;
        const float* a2 = attr + 3 * ids.z;
        o0 = u * a0[0] + v * a1[0] + w * a2[0];
        o1 = u * a0[1] + v * a1[1] + w * a2[1];
        o2 = u * a0[2] + v * a1[2] + w * a2[2];
    }

    int pix = row * res + col;
    out[3 * pix + 0] = o0;
    out[3 * pix + 1] = o1;
    out[3 * pix + 2] = o2;
}

// ------------------------------- launch -----------------------------------
extern "C" void kernel_launch(void* const* d_in, const int* in_sizes, int n_in,
                              void* d_out, int out_size)
{
    const float* attr = (const float*)d_in[0];
    const float* uv   = (const float*)d_in[1];
    const int*   fidx = (const int*)  d_in[2];
    float*       out  = (float*)      d_out;

    int nf = in_sizes[2] / 3;
    int nf_used = (nf / 64) * 64;          // reference truncates to chunks of 64
    if (nf_used > MAX_F) nf_used = MAX_F;

    int res = (int)(sqrt((double)out_size / 3.0) + 0.5);
    int ntx = (res + TS - 1) / TS;
    int ntiles = ntx * ntx;

    if (nf_used > 0) {
        int sblocks = (nf_used + 127) / 128;
        tb_setup_kernel<<<sblocks, 128>>>(uv, fidx, nf_used);
    }

    // PDL launch: bake prologue overlaps setup; it gates on
    // cudaGridDependencySynchronize() before reading setup outputs.
    cudaLaunchConfig_t cfg = {};
    cfg.gridDim  = dim3((unsigned)ntiles, 1, 1);
    cfg.blockDim = dim3(256, 1, 1);
    cfg.dynamicSmemBytes = 0;
    cfg.stream = 0;
    cudaLaunchAttribute at[1];
    at[0].id = cudaLaunchAttributeProgrammaticStreamSerialization;
    at[0].val.programmaticStreamSerializationAllowed = 1;
    cfg.attrs = at;
    cfg.numAttrs = 1;
    cudaLaunchKernelEx(&cfg, tb_bake_kernel, attr, nf_used, res, ntx, out);
}

// round 7
// speedup vs baseline: 2.7870x; 2.7870x over previous
#include <cuda_runtime.h>
#include <math.h>

// ---------------------------------------------------------------------------
// TextureBaker — 2 kernels (R5 structure + single-wave occupancy + PDL).
//  1) tb_setup : cheap per-triangle setup -> 48B record (+tri id), ids, bbox.
//  2) tb_bake  : block = 16x16 pixel tile, __launch_bounds__(256,7) so all
//       1024 blocks fit in ONE wave (148 SMs * 7 = 1036).
//       Phase A : bbox rejection (coalesced float4), stable compaction.
//       Phase A2: SAT refine on bbox survivors, stable compaction.
//       Phase B : copy surviving 48B records into smem.
//       Phase C : per-pixel first-hit scan (early exit) + attr interpolation.
//  Bake launched with PDL (programmatic stream serialization) to overlap the
//  setup kernel; it gates on cudaGridDependencySynchronize() before reading
//  setup outputs. Scan FP expressions identical to prior passing kernels.
// ---------------------------------------------------------------------------

#define MAX_F  8192
#define TS     16
#define SCAP   256     // records per smem batch in phase B/C

__device__ float4 g_rec [MAX_F * 3];  // [ax ay v0x v0y][v1x v1y d00 d01][d11 inv tid 0]
__device__ int4   g_ids [MAX_F];
__device__ float4 g_bbox[MAX_F];      // (minx, maxx, miny, maxy)

// ------------------------------- setup ------------------------------------
__global__ void tb_setup_kernel(const float* __restrict__ uv,
                                const int*   __restrict__ fidx,
                                int nf)
{
    int t = blockIdx.x * blockDim.x + threadIdx.x;
    if (t >= nf) return;

    int i0 = fidx[3 * t + 0];
    int i1 = fidx[3 * t + 1];
    int i2 = fidx[3 * t + 2];

    float ax = uv[2 * i0], ay = uv[2 * i0 + 1];
    float bx = uv[2 * i1], by = uv[2 * i1 + 1];
    float cx = uv[2 * i2], cy = uv[2 * i2 + 1];

    float v0x = bx - ax, v0y = by - ay;
    float v1x = cx - ax, v1y = cy - ay;

    float d00 = v0x * v0x + v0y * v0y;
    float d01 = v0x * v1x + v0y * v1y;
    float d11 = v1x * v1x + v1y * v1y;
    float denom = d00 * d11 - d01 * d01;

    // Degenerate triangle -> NaN inv -> inside test always false (matches ref).
    float inv = (fabsf(denom) < 1e-12f) ? __int_as_float(0x7fc00000)
                                        : (1.0f / denom);

    g_rec[3 * t + 0] = make_float4(ax, ay, v0x, v0y);
    g_rec[3 * t + 1] = make_float4(v1x, v1y, d00, d01);
    g_rec[3 * t + 2] = make_float4(d11, inv, __int_as_float(t), 0.0f);
    g_ids[t] = make_int4(i0, i1, i2, 0);

    float4 bb;
    bb.x = fminf(ax, fminf(bx, cx));
    bb.y = fmaxf(ax, fmaxf(bx, cx));
    bb.z = fminf(ay, fminf(by, cy));
    bb.w = fmaxf(ay, fmaxf(by, cy));
    g_bbox[t] = bb;
}

// ----------------------------- SAT helper ---------------------------------
__device__ __forceinline__ bool rect_outside_edge(
    float px, float py, float qx, float qy, float rx, float ry,
    float x0, float y0, float x1, float y1)
{
    float ex = qx - px, ey = qy - py;
    float sr  = ex * (ry - py) - ey * (rx - px);
    float s00 = ex * (y0 - py) - ey * (x0 - px);
    float s01 = ex * (y1 - py) - ey * (x0 - px);
    float s10 = ex * (y0 - py) - ey * (x1 - px);
    float s11 = ex * (y1 - py) - ey * (x1 - px);
    float mx = fmaxf(fmaxf(s00, s01), fmaxf(s10, s11));
    float mn = fminf(fminf(s00, s01), fminf(s10, s11));
    if (sr > 0.0f) return mx < 0.0f;   // whole rect strictly on far side
    if (sr < 0.0f) return mn > 0.0f;
    return false;                      // degenerate edge: keep (conservative)
}

// -------------------------------- bake ------------------------------------
__global__ void __launch_bounds__(256, 7)
tb_bake_kernel(const float* __restrict__ attr,
               int nf, int res, int ntx,
               float* __restrict__ out)
{
    __shared__ float4 s_rec[SCAP * 3];  // 12 KB
    __shared__ int    s_idx [512];
    __shared__ int    s_idx2[512];
    __shared__ int    s_tot[16];

    int tile = blockIdx.x;
    int tx = tile % ntx;
    int ty = tile / ntx;
    int tid  = threadIdx.x;
    int lane = tid & 31;
    int wid  = tid >> 5;
    unsigned lmask = (1u << lane) - 1u;

    const float eps = 1e-5f;
    float rinv = 1.0f / (float)res;
    float x0 = (float)(tx * TS)      * rinv - eps;
    float x1 = (float)(tx * TS + TS) * rinv + eps;
    float y0 = (float)(ty * TS)      * rinv - eps;
    float y1 = (float)(ty * TS + TS) * rinv + eps;

    int col = tx * TS + (tid & (TS - 1));
    int row = ty * TS + (tid >> 4);
    bool valid = (col < res) && (row < res);
    float pxx = ((float)col + 0.5f) * rinv;
    float pxy = ((float)row + 0.5f) * rinv;

    int   hitT = 0;
    float u = 0.0f, v = 0.0f, w = 0.0f;
    bool  found = false;

    // PDL: wait for setup outputs before reading g_* arrays.
    cudaGridDependencySynchronize();

    for (int chunk = 0; chunk < nf; chunk += 512) {
        __syncthreads();

        // ---- Phase A: bbox rejection, combined stable compaction ----
        int t0 = chunk + tid;
        int t1 = t0 + 256;
        bool k0 = false, k1 = false;
        if (t0 < nf) {
            float4 bb = g_bbox[t0];
            k0 = !(bb.x > x1 || bb.y < x0 || bb.z > y1 || bb.w < y0);
        }
        if (t1 < nf) {
            float4 bb = g_bbox[t1];
            k1 = !(bb.x > x1 || bb.y < x0 || bb.z > y1 || bb.w < y0);
        }
        unsigned b0 = __ballot_sync(0xffffffffu, k0);
        unsigned b1 = __ballot_sync(0xffffffffu, k1);
        if (lane == 0) { s_tot[wid] = __popc(b0); s_tot[8 + wid] = __popc(b1); }
        __syncthreads();

        int pre0 = 0, tot0 = 0, pre1 = 0, tot1 = 0;
        #pragma unroll
        for (int k = 0; k < 8; k++) {
            int a = s_tot[k], b = s_tot[8 + k];
            tot0 += a; tot1 += b;
            pre0 += (k < wid) ? a : 0;
            pre1 += (k < wid) ? b : 0;
        }
        if (k0) s_idx[pre0 + __popc(b0 & lmask)] = t0;
        if (k1) s_idx[tot0 + pre1 + __popc(b1 & lmask)] = t1;
        __syncthreads();
        int bn = tot0 + tot1;

        // ---- Phase A2: SAT refine on bbox survivors ----
        int bn2 = 0;
        for (int base = 0; base < bn; base += 256) {
            int  e = base + tid;
            bool keep = false;
            if (e < bn) {
                int t = s_idx[e];
                float4 a4 = g_rec[3 * t + 0];           // ax ay v0x v0y
                float4 b4 = g_rec[3 * t + 1];           // v1x v1y d00 d01
                float ax = a4.x,        ay = a4.y;
                float bx = ax + a4.z,   by = ay + a4.w;
                float cx = ax + b4.x,   cy = ay + b4.y;
                keep = !(rect_outside_edge(ax, ay, bx, by, cx, cy, x0, y0, x1, y1) ||
                         rect_outside_edge(bx, by, cx, cy, ax, ay, x0, y0, x1, y1) ||
                         rect_outside_edge(cx, cy, ax, ay, bx, by, x0, y0, x1, y1));
            }
            unsigned bal = __ballot_sync(0xffffffffu, keep);
            if (lane == 0) s_tot[wid] = __popc(bal);
            __syncthreads();
            int pre = 0, tot = 0;
            #pragma unroll
            for (int k = 0; k < 8; k++) {
                int a = s_tot[k];
                tot += a;
                pre += (k < wid) ? a : 0;
            }
            if (keep) s_idx2[bn2 + pre + __popc(bal & lmask)] = s_idx[e];
            __syncthreads();
            bn2 += tot;
        }

        // ---- Phase B + C: batched copy + first-hit scan ----
        for (int base = 0; base < bn2; base += SCAP) {
            int m = min(SCAP, bn2 - base);

            __syncthreads();
            for (int r = tid; r < m; r += 256) {
                int t = s_idx2[base + r];
                s_rec[3 * r + 0] = g_rec[3 * t + 0];
                s_rec[3 * r + 1] = g_rec[3 * t + 1];
                s_rec[3 * r + 2] = g_rec[3 * t + 2];
            }
            __syncthreads();

            if (!found && valid) {
                for (int j = 0; j < m; j++) {
                    float4 q0 = s_rec[3 * j + 0];   // ax ay v0x v0y
                    float4 q1 = s_rec[3 * j + 1];   // v1x v1y d00 d01
                    float4 q2 = s_rec[3 * j + 2];   // d11 inv tid 0

                    float v2x = pxx - q0.x;
                    float v2y = pxy - q0.y;
                    float d20 = v2x * q0.z + v2y * q0.w;
                    float d21 = v2x * q1.x + v2y * q1.y;
                    float vv  = (q2.x * d20 - q1.w * d21) * q2.y;
                    float ww  = (q1.z * d21 - q1.w * d20) * q2.y;
                    float uu  = 1.0f - vv - ww;
                    if (uu >= 0.0f && vv >= 0.0f && ww >= 0.0f) {
                        found = true;
                        u = uu; v = vv; w = ww;
                        hitT = __float_as_int(q2.z);
                        break;
                    }
                }
            }
            if (__syncthreads_and(found || !valid)) break;
        }
        if (__syncthreads_and(found || !valid)) break;
    }

    if (!valid) return;

    float o0 = 0.0f, o1 = 0.0f, o2 = 0.0f;
    if (found) {
        int4 ids = g_ids[hitT];
        const float* a0 = attr + 3 * ids.x;
        const float* a1 = attr + 3 * ids.y;
        const float* a2 = attr + 3 * ids.z;
        o0 = u * a0[0] + v * a1[0] + w * a2[0];
        o1 = u * a0[1] + v * a1[1] + w * a2[1];
        o2 = u * a0[2] + v * a1[2] + w * a2[2];
    }

    int pix = row * res + col;
    out[3 * pix + 0] = o0;
    out[3 * pix + 1] = o1;
    out[3 * pix + 2] = o2;
}

// ------------------------------- launch -----------------------------------
extern "C" void kernel_launch(void* const* d_in, const int* in_sizes, int n_in,
                              void* d_out, int out_size)
{
    const float* attr = (const float*)d_in[0];
    const float* uv   = (const float*)d_in[1];
    const int*   fidx = (const int*)  d_in[2];
    float*       out  = (float*)      d_out;

    int nf = in_sizes[2] / 3;
    int nf_used = (nf / 64) * 64;          // reference truncates to chunks of 64
    if (nf_used > MAX_F) nf_used = MAX_F;

    int res = (int)(sqrt((double)out_size / 3.0) + 0.5);
    int ntx = (res + TS - 1) / TS;
    int ntiles = ntx * ntx;

    if (nf_used > 0) {
        int sblocks = (nf_used + 127) / 128;
        tb_setup_kernel<<<sblocks, 128>>>(uv, fidx, nf_used);
    }

    // PDL launch: overlap bake prologue with setup.
    cudaLaunchConfig_t cfg = {};
    cfg.gridDim  = dim3((unsigned)ntiles, 1, 1);
    cfg.blockDim = dim3(256, 1, 1);
    cfg.dynamicSmemBytes = 0;
    cfg.stream = 0;
    cudaLaunchAttribute at[1];
    at[0].id = cudaLaunchAttributeProgrammaticStreamSerialization;
    at[0].val.programmaticStreamSerializationAllowed = 1;
    cfg.attrs = at;
    cfg.numAttrs = 1;
    cudaLaunchKernelEx(&cfg, tb_bake_kernel, attr, nf_used, res, ntx, out);
}